// round 5
// baseline (speedup 1.0000x reference)
#include <cuda_runtime.h>
#include <cstdint>
#include <cstddef>

// Problem dims
#define B_ 2
#define M_ 384
#define N_ 96
#define D_ 512
#define J_ 640
#define C_ 1024
#define MN_ (M_*N_)        // 36864
#define RTOT_ (B_*MN_)     // 73728

// Join tiling: BM=128 x BN=256 x BK=32, 256 threads, 8 warps (2m x 4n), warp 64x64
#define BM 128
#define BN 256
#define BK 32
#define NKT (J_/BK)        // 20
#define THREADS 256

// packed h layout [ks][c][row][p] in words: p innermost (pair k=8ks+c+4p)
#define H_C_STRIDE 264          // 128 rows * 2 + 8 pad ; 264 % 32 == 8
#define H_KS_STRIDE (4*H_C_STRIDE + 8)   // 1064 ; % 32 == 8
#define HS_WORDS (4*H_KS_STRIDE)         // 4256
#define HS_BYTES (HS_WORDS*4)            // 17024

// w layout [k][col] padded
#define WS_STRIDE 264           // 264 % 32 == 8 -> conflict-free b loads
#define WS_BYTES (BK*WS_STRIDE*4)        // 33792

// smem byte offsets
#define SM_AOFF  0
#define SM_TOFF  512
#define SM_HS    1024
#define SM_WS    (SM_HS + 2*HS_BYTES)    // 35072
#define SMEM_TOTAL (SM_WS + 2*WS_BYTES)  // 102656

// Scratch (device globals)
__device__ float g_a[B_*M_*J_];
__device__ float g_t[B_*N_*J_];
__device__ float g_wr[(size_t)J_*C_];   // w_join tf32-RNA-rounded

// ---------------------------------------------------------------------------
// helpers
// ---------------------------------------------------------------------------
__device__ __forceinline__ uint32_t smem_u32(const void* p) {
    uint32_t a;
    asm("{ .reg .u64 t; cvta.to.shared.u64 t, %1; cvt.u32.u64 %0, t; }"
        : "=r"(a) : "l"(p));
    return a;
}
__device__ __forceinline__ unsigned f2tf32(float x) {
    unsigned r;
    asm("cvt.rna.tf32.f32 %0, %1;" : "=r"(r) : "f"(x));
    return r;
}
__device__ __forceinline__ float fast_tanh(float x) {
    float r;
    asm("tanh.approx.f32 %0, %1;" : "=f"(r) : "f"(x));
    return r;
}
__device__ __forceinline__ void mma_tf32(float d[4],
                                         unsigned a0, unsigned a1, unsigned a2, unsigned a3,
                                         unsigned b0, unsigned b1) {
    asm volatile(
        "mma.sync.aligned.m16n8k8.row.col.f32.tf32.tf32.f32 "
        "{%0,%1,%2,%3}, {%4,%5,%6,%7}, {%8,%9}, {%0,%1,%2,%3};"
        : "+f"(d[0]), "+f"(d[1]), "+f"(d[2]), "+f"(d[3])
        : "r"(a0), "r"(a1), "r"(a2), "r"(a3), "r"(b0), "r"(b1));
}
__device__ __forceinline__ void cp_async16(uint32_t dst, const void* src) {
    asm volatile("cp.async.ca.shared.global [%0], [%1], 16;" :: "r"(dst), "l"(src));
}
#define CP_COMMIT() asm volatile("cp.async.commit_group;" ::: "memory")
#define CP_WAIT0()  asm volatile("cp.async.wait_group 0;" ::: "memory")

// ---------------------------------------------------------------------------
// w_join -> tf32-rounded copy
// ---------------------------------------------------------------------------
__global__ __launch_bounds__(256) void wround_kernel(const float* __restrict__ wj) {
    size_t i = (size_t)blockIdx.x * 1024 + threadIdx.x * 4;
    float4 v = *(const float4*)(wj + i);
    uint4 q;
    q.x = f2tf32(v.x); q.y = f2tf32(v.y); q.z = f2tf32(v.z); q.w = f2tf32(v.w);
    *(uint4*)((unsigned*)g_wr + i) = q;
}

// ---------------------------------------------------------------------------
// Projection: out[rows,J] = x[rows,D] @ w[D,J] + bias. 4 rows/block, J split 2.
// ---------------------------------------------------------------------------
__global__ __launch_bounds__(320) void proj_kernel(
    const float* __restrict__ x, const float* __restrict__ w,
    const float* __restrict__ bias, int which)
{
    __shared__ float xs[4][D_];
    float* outp = which ? g_t : g_a;
    const int r0 = blockIdx.x * 4;
    const int j  = blockIdx.y * 320 + threadIdx.x;

    for (int i = threadIdx.x; i < 4 * D_; i += 320)
        xs[i >> 9][i & (D_ - 1)] = x[(r0 + (i >> 9)) * D_ + (i & (D_ - 1))];
    __syncthreads();

    float a0 = 0.f, a1 = 0.f, a2 = 0.f, a3 = 0.f;
#pragma unroll 8
    for (int k = 0; k < D_; ++k) {
        float wv = w[(size_t)k * J_ + j];
        a0 += xs[0][k] * wv; a1 += xs[1][k] * wv;
        a2 += xs[2][k] * wv; a3 += xs[3][k] * wv;
    }
    float bb = bias[j];
    outp[(r0 + 0) * J_ + j] = a0 + bb;
    outp[(r0 + 1) * J_ + j] = a1 + bb;
    outp[(r0 + 2) * J_ + j] = a2 + bb;
    outp[(r0 + 3) * J_ + j] = a3 + bb;
}

// ---------------------------------------------------------------------------
// Fused join GEMM. 256 threads, 8 warps (2m x 4n), warp tile 64x64.
// ---------------------------------------------------------------------------
__global__ __launch_bounds__(THREADS, 1) void join_kernel(
    const float* __restrict__ bj, float* __restrict__ out)
{
    extern __shared__ char sm[];
    const uint32_t sb = smem_u32(sm);
    const int tid  = threadIdx.x;
    const int wid  = tid >> 5;
    const int lane = tid & 31;
    const int col0 = blockIdx.x * BN;
    const int row0 = blockIdx.y * BM;

    int* aoffS = (int*)(sm + SM_AOFF);
    int* toffS = (int*)(sm + SM_TOFF);
    if (tid < BM) {
        int gr  = row0 + tid;
        int b   = gr / MN_;
        int rem = gr - b * MN_;
        int m   = rem / N_;
        int n   = rem - m * N_;
        aoffS[tid] = (b * M_ + m) * J_;
        toffS[tid] = (b * N_ + n) * J_;
    }
    __syncthreads();

    // fill mapping: 2 threads per row, each covers 16 consecutive k
    const int hrow = tid >> 1;           // 0..127
    const int kh   = (tid & 1) * 16;     // 0 or 16
    const int ks0  = (tid & 1) * 2;      // base ks for this thread's half
    const int aoff = aoffS[hrow];
    const int toff = toffS[hrow];

    // warp compute mapping
    const int wm = wid & 1;              // 0..1 (64 rows each)
    const int wn = wid >> 1;             // 0..3 (64 cols each)
    const int g  = lane >> 2;
    const int c  = lane & 3;

    float acc[4][8][4];
#pragma unroll
    for (int mi = 0; mi < 4; ++mi)
#pragma unroll
        for (int ni = 0; ni < 8; ++ni)
#pragma unroll
            for (int q = 0; q < 4; ++q) acc[mi][ni][q] = 0.f;

    // h-store base (words) for this thread's (ks0, row)
    unsigned* const hs0 = (unsigned*)(sm + SM_HS);
    const int hst_base = ks0 * H_KS_STRIDE + hrow * 2;

    // ---------------- prologue: tile 0 ----------------
    {
        float va[16], vt[16];
        *(float4*)&va[0]  = *(const float4*)(g_a + aoff + kh);
        *(float4*)&va[4]  = *(const float4*)(g_a + aoff + kh + 4);
        *(float4*)&va[8]  = *(const float4*)(g_a + aoff + kh + 8);
        *(float4*)&va[12] = *(const float4*)(g_a + aoff + kh + 12);
        *(float4*)&vt[0]  = *(const float4*)(g_t + toff + kh);
        *(float4*)&vt[4]  = *(const float4*)(g_t + toff + kh + 4);
        *(float4*)&vt[8]  = *(const float4*)(g_t + toff + kh + 8);
        *(float4*)&vt[12] = *(const float4*)(g_t + toff + kh + 12);

        uint32_t wbase = sb + SM_WS;
#pragma unroll
        for (int p = 0; p < 8; ++p) {
            int cid  = tid + p * THREADS;        // 0..2047
            int krow = cid >> 6;
            int colf = (cid & 63) * 4;
            cp_async16(wbase + (krow * WS_STRIDE + colf) * 4,
                       g_wr + (size_t)krow * C_ + col0 + colf);
        }
        CP_COMMIT();

#pragma unroll
        for (int ksl = 0; ksl < 2; ++ksl)
#pragma unroll
            for (int cc = 0; cc < 4; ++cc) {
                int kl = ksl * 8 + cc;
                uint2 q;
                q.x = f2tf32(fast_tanh(va[kl]     + vt[kl]));
                q.y = f2tf32(fast_tanh(va[kl + 4] + vt[kl + 4]));
                *(uint2*)(hs0 + hst_base + ksl * H_KS_STRIDE + cc * H_C_STRIDE) = q;
            }
        CP_WAIT0();
        __syncthreads();
    }

    // ---------------- main loop ----------------
    for (int kt = 0; kt < NKT; ++kt) {
        const int buf = kt & 1;
        const int nb  = buf ^ 1;
        const unsigned* hsb = (const unsigned*)(sm + SM_HS + buf * HS_BYTES);
        const unsigned* wsb = (const unsigned*)(sm + SM_WS + buf * WS_BYTES);

        float va[16], vt[16];
        if (kt < NKT - 1) {
            const int k0n = (kt + 1) * BK;
            *(float4*)&va[0]  = *(const float4*)(g_a + aoff + k0n + kh);
            *(float4*)&va[4]  = *(const float4*)(g_a + aoff + k0n + kh + 4);
            *(float4*)&va[8]  = *(const float4*)(g_a + aoff + k0n + kh + 8);
            *(float4*)&va[12] = *(const float4*)(g_a + aoff + k0n + kh + 12);
            *(float4*)&vt[0]  = *(const float4*)(g_t + toff + k0n + kh);
            *(float4*)&vt[4]  = *(const float4*)(g_t + toff + k0n + kh + 4);
            *(float4*)&vt[8]  = *(const float4*)(g_t + toff + k0n + kh + 8);
            *(float4*)&vt[12] = *(const float4*)(g_t + toff + k0n + kh + 12);

            uint32_t wbase = sb + SM_WS + nb * WS_BYTES;
#pragma unroll
            for (int p = 0; p < 8; ++p) {
                int cid  = tid + p * THREADS;
                int krow = cid >> 6;
                int colf = (cid & 63) * 4;
                cp_async16(wbase + (krow * WS_STRIDE + colf) * 4,
                           g_wr + (size_t)(k0n + krow) * C_ + col0 + colf);
            }
            CP_COMMIT();
        }

        // compute current tile
#pragma unroll
        for (int ks = 0; ks < BK / 8; ++ks) {
            unsigned a_frag[4][4];
            const int abase = ks * H_KS_STRIDE + c * H_C_STRIDE;
#pragma unroll
            for (int mi = 0; mi < 4; ++mi) {
                int rlo = wm * 64 + mi * 16 + g;
                uint2 u0 = *(const uint2*)(hsb + abase + rlo * 2);
                uint2 u1 = *(const uint2*)(hsb + abase + (rlo + 8) * 2);
                a_frag[mi][0] = u0.x; a_frag[mi][2] = u0.y;
                a_frag[mi][1] = u1.x; a_frag[mi][3] = u1.y;
            }
#pragma unroll
            for (int ni = 0; ni < 8; ++ni) {
                int ncol = wn * 64 + ni * 8 + g;
                unsigned b0 = wsb[(ks * 8 + c)     * WS_STRIDE + ncol];
                unsigned b1 = wsb[(ks * 8 + c + 4) * WS_STRIDE + ncol];
#pragma unroll
                for (int mi = 0; mi < 4; ++mi)
                    mma_tf32(acc[mi][ni],
                             a_frag[mi][0], a_frag[mi][1], a_frag[mi][2], a_frag[mi][3],
                             b0, b1);
            }
        }

        // finish next h tile
        if (kt < NKT - 1) {
            unsigned* hd = (unsigned*)(sm + SM_HS + nb * HS_BYTES);
#pragma unroll
            for (int ksl = 0; ksl < 2; ++ksl)
#pragma unroll
                for (int cc = 0; cc < 4; ++cc) {
                    int kl = ksl * 8 + cc;
                    uint2 q;
                    q.x = f2tf32(fast_tanh(va[kl]     + vt[kl]));
                    q.y = f2tf32(fast_tanh(va[kl + 4] + vt[kl + 4]));
                    *(uint2*)(hd + hst_base + ksl * H_KS_STRIDE + cc * H_C_STRIDE) = q;
                }
            CP_WAIT0();
        }
        __syncthreads();
    }

    // ---------------- epilogue ----------------
#pragma unroll
    for (int ni = 0; ni < 8; ++ni) {
        int gcol = col0 + wn * 64 + ni * 8 + c * 2;
        float2 bb = *(const float2*)(bj + gcol);
#pragma unroll
        for (int mi = 0; mi < 4; ++mi) {
            int grow = row0 + wm * 64 + mi * 16 + g;
            float2 v0 = make_float2(acc[mi][ni][0] + bb.x, acc[mi][ni][1] + bb.y);
            float2 v1 = make_float2(acc[mi][ni][2] + bb.x, acc[mi][ni][3] + bb.y);
            *(float2*)(out + (size_t)grow * C_ + gcol)       = v0;
            *(float2*)(out + (size_t)(grow + 8) * C_ + gcol) = v1;
        }
    }
}

// ---------------------------------------------------------------------------
// launch
// ---------------------------------------------------------------------------
extern "C" void kernel_launch(void* const* d_in, const int* in_sizes, int n_in,
                              void* d_out, int out_size)
{
    const float* enc     = (const float*)d_in[0];
    const float* dec     = (const float*)d_in[1];
    const float* w_audio = (const float*)d_in[2];
    const float* b_audio = (const float*)d_in[3];
    const float* w_text  = (const float*)d_in[4];
    const float* b_text  = (const float*)d_in[5];
    const float* w_join  = (const float*)d_in[6];
    const float* b_join  = (const float*)d_in[7];
    float* out = (float*)d_out;

    static int smem_set = 0;
    if (!smem_set) {
        cudaFuncSetAttribute(join_kernel, cudaFuncAttributeMaxDynamicSharedMemorySize,
                             SMEM_TOTAL);
        smem_set = 1;
    }

    wround_kernel<<<(J_ * C_) / 1024, 256>>>(w_join);
    proj_kernel<<<dim3((B_ * M_) / 4, 2), 320>>>(enc, w_audio, b_audio, 0);
    proj_kernel<<<dim3((B_ * N_) / 4, 2), 320>>>(dec, w_text, b_text, 1);

    join_kernel<<<dim3(C_ / BN, RTOT_ / BM), THREADS, SMEM_TOTAL>>>(b_join, out);
}